// round 2
// baseline (speedup 1.0000x reference)
#include <cuda_runtime.h>
#include <cstdint>
#include <cstddef>

#define B_ 8192
#define N_ 512

// scratch: per-batch 16 raw moments, then 9 rot + 3 centroid
__device__ float g_red[B_ * 16];
__device__ float g_rt[B_ * 12];

// ---------------------------------------------------------------------------
// Kernel 1: per-batch weighted moment reductions (single streaming pass)
// acc[0..8]  = sum w * tc_i * pc_j   (i*3+j)
// acc[9..11] = sum w * tc_i
// acc[12..14]= sum w * pc_j
// acc[15]    = sum w
// mask is a 4-byte-per-element buffer (int32/float32 bool); nonzero == true.
// ---------------------------------------------------------------------------
__global__ __launch_bounds__(128) void k_reduce(
    const float* __restrict__ pred, const float* __restrict__ truc,
    const float* __restrict__ wgt, const unsigned int* __restrict__ msk)
{
    int b = blockIdx.x, tid = threadIdx.x;
    const float4* tp = reinterpret_cast<const float4*>(truc + (size_t)b * 1536) + tid * 3;
    const float4* pp = reinterpret_cast<const float4*>(pred + (size_t)b * 1536) + tid * 3;

    float4 tv[3], pv[3], wv4;
    tv[0] = tp[0]; tv[1] = tp[1]; tv[2] = tp[2];
    pv[0] = pp[0]; pv[1] = pp[1]; pv[2] = pp[2];
    wv4 = reinterpret_cast<const float4*>(wgt + (size_t)b * 512)[tid];
    uint4 mv = reinterpret_cast<const uint4*>(msk + (size_t)b * 512)[tid];

    const float* ta = reinterpret_cast<const float*>(tv);
    const float* pa = reinterpret_cast<const float*>(pv);
    const float* wa = reinterpret_cast<const float*>(&wv4);
    const unsigned int* ma = reinterpret_cast<const unsigned int*>(&mv);

    float acc[16];
#pragma unroll
    for (int k = 0; k < 16; k++) acc[k] = 0.f;

#pragma unroll
    for (int k = 0; k < 4; k++) {
        float w = ma[k] ? wa[k] : 0.f;
        float tx = ta[3 * k], ty = ta[3 * k + 1], tz = ta[3 * k + 2];
        float px = pa[3 * k], py = pa[3 * k + 1], pz = pa[3 * k + 2];
        float wtx = w * tx, wty = w * ty, wtz = w * tz;
        acc[0] = fmaf(wtx, px, acc[0]); acc[1] = fmaf(wtx, py, acc[1]); acc[2] = fmaf(wtx, pz, acc[2]);
        acc[3] = fmaf(wty, px, acc[3]); acc[4] = fmaf(wty, py, acc[4]); acc[5] = fmaf(wty, pz, acc[5]);
        acc[6] = fmaf(wtz, px, acc[6]); acc[7] = fmaf(wtz, py, acc[7]); acc[8] = fmaf(wtz, pz, acc[8]);
        acc[9] += wtx; acc[10] += wty; acc[11] += wtz;
        acc[12] = fmaf(w, px, acc[12]); acc[13] = fmaf(w, py, acc[13]); acc[14] = fmaf(w, pz, acc[14]);
        acc[15] += w;
    }

#pragma unroll
    for (int k = 0; k < 16; k++) {
#pragma unroll
        for (int o = 16; o > 0; o >>= 1)
            acc[k] += __shfl_xor_sync(0xFFFFFFFFu, acc[k], o);
    }

    __shared__ float sred[4][16];
    int wid = tid >> 5, lane = tid & 31;
    if (lane == 0) {
#pragma unroll
        for (int k = 0; k < 16; k++) sred[wid][k] = acc[k];
    }
    __syncthreads();
    if (tid < 16)
        g_red[b * 16 + tid] = sred[0][tid] + sred[1][tid] + sred[2][tid] + sred[3][tid];
}

// ---------------------------------------------------------------------------
// Kernel 2: one thread per batch -> 3x3 SVD -> rotation + centroid
// ---------------------------------------------------------------------------
__device__ __forceinline__ double drsqrt(double x) {
    double y = (double)rsqrtf((float)x);
    y = y * (1.5 - (0.5 * x) * y * y);
    y = y * (1.5 - (0.5 * x) * y * y);
    return y;
}

// one cyclic Jacobi rotation on symmetric 3x3 (fp32)
#define JROT(app, aqq, apq, arp, arq, vAp, vAq, vBp, vBq, vCp, vCq) do {      \
    float _a = (apq);                                                          \
    if (fabsf(_a) > 1e-12f * (fabsf(app) + fabsf(aqq))) {                      \
        float _th = 0.5f * ((aqq) - (app)) / _a;                               \
        float _t = copysignf(1.f, _th) / (fabsf(_th) + sqrtf(fmaf(_th, _th, 1.f))); \
        float _c = rsqrtf(fmaf(_t, _t, 1.f));                                  \
        float _s = _t * _c;                                                    \
        (app) -= _t * _a; (aqq) += _t * _a; (apq) = 0.f;                       \
        float _rp = (arp), _rq = (arq);                                        \
        (arp) = _c * _rp - _s * _rq; (arq) = _s * _rp + _c * _rq;              \
        float _x;                                                              \
        _x = (vAp); (vAp) = _c * _x - _s * (vAq); (vAq) = _s * _x + _c * (vAq);\
        _x = (vBp); (vBp) = _c * _x - _s * (vBq); (vBq) = _s * _x + _c * (vBq);\
        _x = (vCp); (vCp) = _c * _x - _s * (vCq); (vCq) = _s * _x + _c * (vCq);\
    } } while (0)

__global__ void k_svd()
{
    int b = blockIdx.x * blockDim.x + threadIdx.x;
    if (b >= B_) return;

    float r[16];
#pragma unroll
    for (int k = 0; k < 16; k++) r[k] = g_red[b * 16 + k];

    float sw = r[15];
    float inv = 1.f / sw;
    float c0 = r[9] * inv, c1 = r[10] * inv, c2 = r[11] * inv;  // true centroid

    float cov[9];
#pragma unroll
    for (int i = 0; i < 3; i++)
#pragma unroll
        for (int j = 0; j < 3; j++)
            cov[i * 3 + j] = r[i * 3 + j] - r[9 + i] * r[12 + j] * inv;

    // M = cov^T cov (symmetric fp32)
    float m00 = 0, m01 = 0, m02 = 0, m11 = 0, m12 = 0, m22 = 0;
#pragma unroll
    for (int k = 0; k < 3; k++) {
        float a0 = cov[k * 3 + 0], a1 = cov[k * 3 + 1], a2 = cov[k * 3 + 2];
        m00 = fmaf(a0, a0, m00); m01 = fmaf(a0, a1, m01); m02 = fmaf(a0, a2, m02);
        m11 = fmaf(a1, a1, m11); m12 = fmaf(a1, a2, m12); m22 = fmaf(a2, a2, m22);
    }

    float v00 = 1, v01 = 0, v02 = 0, v10 = 0, v11 = 1, v12 = 0, v20 = 0, v21 = 0, v22 = 1;
#pragma unroll
    for (int sweep = 0; sweep < 5; sweep++) {
        JROT(m00, m11, m01, m02, m12, v00, v01, v10, v11, v20, v21); // (p,q)=(0,1), r=2
        JROT(m00, m22, m02, m01, m12, v00, v02, v10, v12, v20, v22); // (p,q)=(0,2), r=1
        JROT(m11, m22, m12, m01, m02, v01, v02, v11, v12, v21, v22); // (p,q)=(1,2), r=0
    }

    int imin = 0; float lmin = m00;
    if (m11 < lmin) { lmin = m11; imin = 1; }
    if (m22 < lmin) { lmin = m22; imin = 2; }
    int ia = (imin == 0) ? 1 : 0;
    int ib = (imin == 2) ? 1 : 2;

    double vd[9] = { v00, v01, v02, v10, v11, v12, v20, v21, v22 }; // vd[r*3+c], col c = eigvec
    double dc[9];
#pragma unroll
    for (int k = 0; k < 9; k++) dc[k] = (double)cov[k];

    // rebuild the smallest-sigma direction as cross of the two dominant eigvecs
    // (well conditioned even when sigma_min -> 0)
    {
        double ax = vd[0 * 3 + ia], ay = vd[1 * 3 + ia], az = vd[2 * 3 + ia];
        double bx = vd[0 * 3 + ib], by = vd[1 * 3 + ib], bz = vd[2 * 3 + ib];
        double cx = ay * bz - az * by;
        double cy = az * bx - ax * bz;
        double cz = ax * by - ay * bx;
        double inm = drsqrt(cx * cx + cy * cy + cz * cz);
        vd[0 * 3 + imin] = cx * inm;
        vd[1 * 3 + imin] = cy * inm;
        vd[2 * 3 + imin] = cz * inm;
    }

    double det = dc[0] * (dc[4] * dc[8] - dc[5] * dc[7])
               - dc[1] * (dc[3] * dc[8] - dc[5] * dc[6])
               + dc[2] * (dc[3] * dc[7] - dc[4] * dc[6]);

    double rot[9];
#pragma unroll
    for (int k = 0; k < 9; k++) rot[k] = 0.0;

#pragma unroll
    for (int i = 0; i < 3; i++) {
        // g = cov * v_i ; sigma_i = ||g|| ; u_i = g / sigma_i
        double g0 = dc[0] * vd[0 * 3 + i] + dc[1] * vd[1 * 3 + i] + dc[2] * vd[2 * 3 + i];
        double g1 = dc[3] * vd[0 * 3 + i] + dc[4] * vd[1 * 3 + i] + dc[5] * vd[2 * 3 + i];
        double g2 = dc[6] * vd[0 * 3 + i] + dc[7] * vd[1 * 3 + i] + dc[8] * vd[2 * 3 + i];
        double s2 = g0 * g0 + g1 * g1 + g2 * g2;
        double coef = drsqrt(s2);
        if (i == imin && det < 0.0) coef = -coef;   // reflection fix on smallest sigma
        // rot += coef * v_i * g^T   (== d_i * v_i u_i^T)
        rot[0] += coef * vd[0 * 3 + i] * g0; rot[1] += coef * vd[0 * 3 + i] * g1; rot[2] += coef * vd[0 * 3 + i] * g2;
        rot[3] += coef * vd[1 * 3 + i] * g0; rot[4] += coef * vd[1 * 3 + i] * g1; rot[5] += coef * vd[1 * 3 + i] * g2;
        rot[6] += coef * vd[2 * 3 + i] * g0; rot[7] += coef * vd[2 * 3 + i] * g1; rot[8] += coef * vd[2 * 3 + i] * g2;
    }

#pragma unroll
    for (int k = 0; k < 9; k++) g_rt[b * 12 + k] = (float)rot[k];
    g_rt[b * 12 + 9]  = c0;
    g_rt[b * 12 + 10] = c1;
    g_rt[b * 12 + 11] = c2;
}

// ---------------------------------------------------------------------------
// Kernel 3: apply rotation: out = rot @ (tc_masked - cent) + cent
// ---------------------------------------------------------------------------
__global__ __launch_bounds__(128) void k_apply(
    const float* __restrict__ truc, const unsigned int* __restrict__ msk,
    float* __restrict__ out)
{
    int b = blockIdx.x, tid = threadIdx.x;
    __shared__ float srt[12];
    if (tid < 12) srt[tid] = g_rt[b * 12 + tid];

    const float4* tp = reinterpret_cast<const float4*>(truc + (size_t)b * 1536) + tid * 3;
    float4 tv[3];
    tv[0] = tp[0]; tv[1] = tp[1]; tv[2] = tp[2];
    uint4 mv = reinterpret_cast<const uint4*>(msk + (size_t)b * 512)[tid];
    __syncthreads();

    const float* ta = reinterpret_cast<const float*>(tv);
    const unsigned int* ma = reinterpret_cast<const unsigned int*>(&mv);
    float r00 = srt[0], r01 = srt[1], r02 = srt[2];
    float r10 = srt[3], r11 = srt[4], r12 = srt[5];
    float r20 = srt[6], r21 = srt[7], r22 = srt[8];
    float c0 = srt[9], c1 = srt[10], c2 = srt[11];

    float4 ov[3];
    float* oa = reinterpret_cast<float*>(ov);
#pragma unroll
    for (int k = 0; k < 4; k++) {
        float m = ma[k] ? 1.f : 0.f;
        float x = ta[3 * k] * m - c0;
        float y = ta[3 * k + 1] * m - c1;
        float z = ta[3 * k + 2] * m - c2;
        oa[3 * k + 0] = fmaf(r00, x, fmaf(r01, y, fmaf(r02, z, c0)));
        oa[3 * k + 1] = fmaf(r10, x, fmaf(r11, y, fmaf(r12, z, c1)));
        oa[3 * k + 2] = fmaf(r20, x, fmaf(r21, y, fmaf(r22, z, c2)));
    }

    float4* op = reinterpret_cast<float4*>(out + (size_t)b * 1536) + tid * 3;
    op[0] = ov[0]; op[1] = ov[1]; op[2] = ov[2];
}

// ---------------------------------------------------------------------------
extern "C" void kernel_launch(void* const* d_in, const int* in_sizes, int n_in,
                              void* d_out, int out_size)
{
    const float* pred = (const float*)d_in[0];
    const float* truc = (const float*)d_in[1];
    const float* wgt  = (const float*)d_in[2];
    const unsigned int* msk = (const unsigned int*)d_in[3];
    float* out = (float*)d_out;

    k_reduce<<<B_, 128>>>(pred, truc, wgt, msk);
    k_svd<<<(B_ + 255) / 256, 256>>>();
    k_apply<<<B_, 128>>>(truc, msk, out);
}